// round 3
// baseline (speedup 1.0000x reference)
#include <cuda_runtime.h>
#include <cuda_bf16.h>
#include <math.h>

#define Bq   8
#define Tq   2048
#define Dq   1024
#define HSq  128
#define BT   (Bq * Tq)        // 16384 rows

// Scratch for projected q, k, v (fp32). __device__ globals per harness rules.
__device__ float g_q[BT * HSq];
__device__ float g_k[BT * HSq];
__device__ float g_v[BT * HSq];

// ---------------------------------------------------------------------------
// Kernel 1: fused QKV projection.
// GEMM: [16384 x 1024] @ [1024 x 384] -> g_q | g_k | g_v
// Grid: (BT/64, 6). Block 256 threads. BM=64, BN=64, BK=32.
// Thread micro-tile: 4 rows (ty*4+i) x 4 cols (tx + 16*j, strided -> conflict-free LDS)
// ---------------------------------------------------------------------------
__global__ __launch_bounds__(256) void proj_kernel(
    const float* __restrict__ x,
    const float* __restrict__ Wq,
    const float* __restrict__ Wk,
    const float* __restrict__ Wv)
{
    __shared__ float Xs[64][33];
    __shared__ float Ws[32][65];

    const int m0 = blockIdx.x * 64;
    const int nt = blockIdx.y;                    // 0..5 -> which 64-col slab of [q|k|v]
    const float* W = (nt < 2) ? Wq : (nt < 4) ? Wk : Wv;
    float* outp    = (nt < 2) ? g_q : (nt < 4) ? g_k : g_v;
    const int ncol0 = (nt & 1) * 64;              // col offset within HS=128

    const int tid = threadIdx.x;
    const int tx = tid & 15;
    const int ty = tid >> 4;

    float acc[4][4] = {};

    for (int kt = 0; kt < Dq; kt += 32) {
        // Load Xs: 64x32 floats = 512 float4, 2 per thread
        #pragma unroll
        for (int it = 0; it < 2; it++) {
            int idx = tid + it * 256;
            int r  = idx >> 3;         // 8 float4 per row
            int c4 = (idx & 7) * 4;
            float4 v = *(const float4*)&x[(size_t)(m0 + r) * Dq + kt + c4];
            Xs[r][c4 + 0] = v.x; Xs[r][c4 + 1] = v.y;
            Xs[r][c4 + 2] = v.z; Xs[r][c4 + 3] = v.w;
        }
        // Load Ws: 32x64 floats = 512 float4, 2 per thread
        #pragma unroll
        for (int it = 0; it < 2; it++) {
            int idx = tid + it * 256;
            int r  = idx >> 4;         // 16 float4 per row
            int c4 = (idx & 15) * 4;
            float4 v = *(const float4*)&W[(size_t)(kt + r) * HSq + ncol0 + c4];
            Ws[r][c4 + 0] = v.x; Ws[r][c4 + 1] = v.y;
            Ws[r][c4 + 2] = v.z; Ws[r][c4 + 3] = v.w;
        }
        __syncthreads();

        #pragma unroll 8
        for (int kk = 0; kk < 32; kk++) {
            float a[4], b[4];
            #pragma unroll
            for (int i = 0; i < 4; i++) a[i] = Xs[ty * 4 + i][kk];
            #pragma unroll
            for (int j = 0; j < 4; j++) b[j] = Ws[kk][tx + 16 * j];
            #pragma unroll
            for (int i = 0; i < 4; i++)
                #pragma unroll
                for (int j = 0; j < 4; j++)
                    acc[i][j] = fmaf(a[i], b[j], acc[i][j]);
        }
        __syncthreads();
    }

    #pragma unroll
    for (int i = 0; i < 4; i++)
        #pragma unroll
        for (int j = 0; j < 4; j++)
            outp[(size_t)(m0 + ty * 4 + i) * HSq + ncol0 + tx + 16 * j] = acc[i][j];
}

// ---------------------------------------------------------------------------
// Kernel 2: causal flash attention, fp32.
// Grid: (16 pairs, 8 batches). Block 256 threads.
// Each block processes q-tiles pair (p) and (31-p): constant 33 KV iterations
// per block -> balanced single wave.
// smem: Qs/Ks/Vs 64x128 padded to stride 129. P aliases Ks.
// ---------------------------------------------------------------------------
#define SM_STRIDE 129
#define ATTN_SMEM (3 * 64 * SM_STRIDE * sizeof(float))

__global__ __launch_bounds__(256) void attn_kernel(float* __restrict__ out)
{
    extern __shared__ float sm[];
    float (*Qs)[SM_STRIDE] = (float (*)[SM_STRIDE])(sm);
    float (*Ks)[SM_STRIDE] = (float (*)[SM_STRIDE])(sm + 64 * SM_STRIDE);
    float (*Vs)[SM_STRIDE] = (float (*)[SM_STRIDE])(sm + 2 * 64 * SM_STRIDE);
    float (*Ps)[SM_STRIDE] = Ks;   // P overwrites K after S-gemm

    const int b    = blockIdx.y;
    const int pair = blockIdx.x;          // 0..15
    const int tid  = threadIdx.x;
    const int tx   = tid & 15;
    const int ty   = tid >> 4;

    const float* qg = g_q + (size_t)b * Tq * HSq;
    const float* kg = g_k + (size_t)b * Tq * HSq;
    const float* vg = g_v + (size_t)b * Tq * HSq;

    const float scale = 0.08838834764831845f;   // 128^-0.5
    const float NEG_INF = -__int_as_float(0x7f800000);

    for (int half = 0; half < 2; half++) {
        const int qt = (half == 0) ? pair : (31 - pair);
        const int q0 = qt * 64;

        __syncthreads();  // previous half's smem reads are done
        // Load Q tile (fold softmax scale into Q)
        #pragma unroll
        for (int it = 0; it < 8; it++) {
            int idx = tid + it * 256;
            int r  = idx >> 5;           // 32 float4 per row
            int c4 = (idx & 31) * 4;
            float4 v = *(const float4*)&qg[(size_t)(q0 + r) * HSq + c4];
            Qs[r][c4 + 0] = v.x * scale; Qs[r][c4 + 1] = v.y * scale;
            Qs[r][c4 + 2] = v.z * scale; Qs[r][c4 + 3] = v.w * scale;
        }

        float acc_o[4][8] = {};
        float m_i[4], l_i[4];
        #pragma unroll
        for (int i = 0; i < 4; i++) { m_i[i] = NEG_INF; l_i[i] = 0.f; }

        const int ktiles = qt + 1;
        for (int kt = 0; kt < ktiles; kt++) {
            const int k0 = kt * 64;

            __syncthreads();  // prior PV reads of Ps(=Ks)/Vs done; Q load done
            // Load K and V tiles
            #pragma unroll
            for (int it = 0; it < 8; it++) {
                int idx = tid + it * 256;
                int r  = idx >> 5;
                int c4 = (idx & 31) * 4;
                float4 kv = *(const float4*)&kg[(size_t)(k0 + r) * HSq + c4];
                Ks[r][c4 + 0] = kv.x; Ks[r][c4 + 1] = kv.y;
                Ks[r][c4 + 2] = kv.z; Ks[r][c4 + 3] = kv.w;
                float4 vv = *(const float4*)&vg[(size_t)(k0 + r) * HSq + c4];
                Vs[r][c4 + 0] = vv.x; Vs[r][c4 + 1] = vv.y;
                Vs[r][c4 + 2] = vv.z; Vs[r][c4 + 3] = vv.w;
            }
            __syncthreads();

            // S = Q K^T  (64x64, per-thread 4x4; n mapping tx+16j)
            float s[4][4] = {};
            #pragma unroll 8
            for (int kk = 0; kk < HSq; kk++) {
                float a[4], bb[4];
                #pragma unroll
                for (int i = 0; i < 4; i++) a[i] = Qs[ty * 4 + i][kk];
                #pragma unroll
                for (int j = 0; j < 4; j++) bb[j] = Ks[tx + 16 * j][kk];
                #pragma unroll
                for (int i = 0; i < 4; i++)
                    #pragma unroll
                    for (int j = 0; j < 4; j++)
                        s[i][j] = fmaf(a[i], bb[j], s[i][j]);
            }

            // Causal mask only on the diagonal tile
            if (kt == qt) {
                #pragma unroll
                for (int i = 0; i < 4; i++)
                    #pragma unroll
                    for (int j = 0; j < 4; j++)
                        if ((tx + 16 * j) > (ty * 4 + i)) s[i][j] = NEG_INF;
            }

            // Online softmax (per row i; 16-lane shfl reductions)
            #pragma unroll
            for (int i = 0; i < 4; i++) {
                float mx = s[i][0];
                mx = fmaxf(mx, s[i][1]); mx = fmaxf(mx, s[i][2]); mx = fmaxf(mx, s[i][3]);
                #pragma unroll
                for (int off = 8; off >= 1; off >>= 1)
                    mx = fmaxf(mx, __shfl_xor_sync(0xffffffffu, mx, off));
                float m_new = fmaxf(m_i[i], mx);
                float alpha = __expf(m_i[i] - m_new);
                float rs = 0.f;
                #pragma unroll
                for (int j = 0; j < 4; j++) {
                    float p = __expf(s[i][j] - m_new);
                    s[i][j] = p;
                    rs += p;
                }
                #pragma unroll
                for (int off = 8; off >= 1; off >>= 1)
                    rs += __shfl_xor_sync(0xffffffffu, rs, off);
                l_i[i] = l_i[i] * alpha + rs;
                m_i[i] = m_new;
                #pragma unroll
                for (int jj = 0; jj < 8; jj++) acc_o[i][jj] *= alpha;
            }

            __syncthreads();  // all S-gemm reads of Ks done before overwriting with P
            #pragma unroll
            for (int i = 0; i < 4; i++)
                #pragma unroll
                for (int j = 0; j < 4; j++)
                    Ps[ty * 4 + i][tx + 16 * j] = s[i][j];
            __syncthreads();

            // O += P @ V   (64x128, per-thread 4 rows x 8 cols [tx+16jj])
            #pragma unroll 4
            for (int n = 0; n < 64; n++) {
                float pr[4], vv[8];
                #pragma unroll
                for (int i = 0; i < 4; i++) pr[i] = Ps[ty * 4 + i][n];
                #pragma unroll
                for (int jj = 0; jj < 8; jj++) vv[jj] = Vs[n][tx + 16 * jj];
                #pragma unroll
                for (int i = 0; i < 4; i++)
                    #pragma unroll
                    for (int jj = 0; jj < 8; jj++)
                        acc_o[i][jj] = fmaf(pr[i], vv[jj], acc_o[i][jj]);
            }
        }

        // Epilogue: normalize and store
        #pragma unroll
        for (int i = 0; i < 4; i++) {
            float inv = __frcp_rn(l_i[i]);
            int row = q0 + ty * 4 + i;
            #pragma unroll
            for (int jj = 0; jj < 8; jj++)
                out[((size_t)b * Tq + row) * HSq + tx + 16 * jj] = acc_o[i][jj] * inv;
        }
    }
}

// ---------------------------------------------------------------------------
extern "C" void kernel_launch(void* const* d_in, const int* in_sizes, int n_in,
                              void* d_out, int out_size)
{
    const float* x  = (const float*)d_in[0];
    const float* Wq = (const float*)d_in[1];
    const float* Wk = (const float*)d_in[2];
    const float* Wv = (const float*)d_in[3];
    float* out = (float*)d_out;

    cudaFuncSetAttribute(attn_kernel, cudaFuncAttributeMaxDynamicSharedMemorySize,
                         (int)ATTN_SMEM);

    dim3 pgrid(BT / 64, 6);
    proj_kernel<<<pgrid, 256>>>(x, Wq, Wk, Wv);

    dim3 agrid(16, Bq);
    attn_kernel<<<agrid, 256, ATTN_SMEM>>>(out);
}

// round 5
// speedup vs baseline: 2.1147x; 2.1147x over previous
#include <cuda_runtime.h>
#include <cuda_bf16.h>
#include <math.h>
#include <cstdint>

#define Bq   8
#define Tq   2048
#define Dq   1024
#define HSq  128
#define BT   (Bq * Tq)        // 16384 rows
#define NTOT 384              // 3 * HS

// Scratch (device globals — no allocs allowed).
__device__ float g_q[BT * HSq];
__device__ float g_k[BT * HSq];
__device__ float g_v[BT * HSq];
__device__ __nv_bfloat16 g_wt_hi[NTOT * Dq];   // W^T, K-major, bf16 hi
__device__ __nv_bfloat16 g_wt_lo[NTOT * Dq];   // W^T, K-major, bf16 lo

// ---------------------------------------------------------------------------
// Warp-MMA helpers (sm_80+ features, safe on baseline compute_103 target)
// ---------------------------------------------------------------------------
__device__ __forceinline__ void mma_bf16(float* c, const uint32_t* a, const uint32_t* b) {
    asm volatile(
        "mma.sync.aligned.m16n8k16.row.col.f32.bf16.bf16.f32 "
        "{%0,%1,%2,%3}, {%4,%5,%6,%7}, {%8,%9}, {%0,%1,%2,%3};"
        : "+f"(c[0]), "+f"(c[1]), "+f"(c[2]), "+f"(c[3])
        : "r"(a[0]), "r"(a[1]), "r"(a[2]), "r"(a[3]), "r"(b[0]), "r"(b[1]));
}
__device__ __forceinline__ void ldsm_x2(uint32_t& r0, uint32_t& r1, uint32_t addr) {
    asm volatile("ldmatrix.sync.aligned.m8n8.x2.shared.b16 {%0,%1}, [%2];"
                 : "=r"(r0), "=r"(r1) : "r"(addr));
}
__device__ __forceinline__ void ldsm_x2_t(uint32_t& r0, uint32_t& r1, uint32_t addr) {
    asm volatile("ldmatrix.sync.aligned.m8n8.x2.trans.shared.b16 {%0,%1}, [%2];"
                 : "=r"(r0), "=r"(r1) : "r"(addr));
}
__device__ __forceinline__ uint32_t smem_u32(const void* p) {
    uint32_t a;
    asm("{ .reg .u64 t; cvta.to.shared.u64 t, %1; cvt.u32.u64 %0, t; }"
        : "=r"(a) : "l"(p));
    return a;
}
__device__ __forceinline__ uint32_t pack_bf2(float a, float b) {
    __nv_bfloat162 h = __floats2bfloat162_rn(a, b);
    return *(uint32_t*)&h;
}
// split one float into (hi, lo) bf16 packed helpers
__device__ __forceinline__ void split2(float v0, float v1, uint32_t& hi, uint32_t& lo) {
    __nv_bfloat16 h0 = __float2bfloat16_rn(v0);
    __nv_bfloat16 h1 = __float2bfloat16_rn(v1);
    float l0 = v0 - __bfloat162float(h0);
    float l1 = v1 - __bfloat162float(h1);
    hi = (uint32_t)__bfloat16_as_ushort(h0) | ((uint32_t)__bfloat16_as_ushort(h1) << 16);
    __nv_bfloat16 g0 = __float2bfloat16_rn(l0);
    __nv_bfloat16 g1 = __float2bfloat16_rn(l1);
    lo = (uint32_t)__bfloat16_as_ushort(g0) | ((uint32_t)__bfloat16_as_ushort(g1) << 16);
}

// ---------------------------------------------------------------------------
// Kernel 0: transpose + split-convert weights.
// Wq|Wk|Wv [1024 x 128] fp32 -> g_wt_hi/lo [384 x 1024] bf16 (K-major).
// ---------------------------------------------------------------------------
__global__ void prep_w_kernel(const float* __restrict__ Wq,
                              const float* __restrict__ Wk,
                              const float* __restrict__ Wv)
{
    __shared__ float t[32][33];
    const int k0 = blockIdx.x * 32;
    const int n0 = blockIdx.y * 32;
    const int slab = n0 >> 7;
    const float* W = (slab == 0) ? Wq : (slab == 1) ? Wk : Wv;
    const int nn0 = n0 & 127;
    const int tx = threadIdx.x, ty = threadIdx.y;

    #pragma unroll
    for (int i = 0; i < 4; i++)
        t[ty * 4 + i][tx] = W[(size_t)(k0 + ty * 4 + i) * HSq + nn0 + tx];
    __syncthreads();
    #pragma unroll
    for (int i = 0; i < 4; i++) {
        int nr = ty * 4 + i;
        float v = t[tx][nr];
        __nv_bfloat16 hi = __float2bfloat16_rn(v);
        __nv_bfloat16 lo = __float2bfloat16_rn(v - __bfloat162float(hi));
        size_t o = (size_t)(n0 + nr) * Dq + k0 + tx;
        g_wt_hi[o] = hi;
        g_wt_lo[o] = lo;
    }
}

// ---------------------------------------------------------------------------
// Kernel 1: QKV projection with HMMA (mma.sync bf16, 3-term split).
// C[16384 x 384] = X @ W.  Grid (128 M-tiles, 3 slabs), block 256 (8 warps).
// BM=128, BN=128, BK=32. Warp grid 4x2; warp tile 32x64 (2 m-tiles x 8 n-tiles).
// ---------------------------------------------------------------------------
#define XS_STRIDE 40   // bf16 elems per row (32 + 8 pad) -> conflict-free frag LDS

__global__ __launch_bounds__(256) void proj_mma_kernel(const float* __restrict__ x)
{
    __shared__ __align__(16) __nv_bfloat16 Xs_hi[128][XS_STRIDE];
    __shared__ __align__(16) __nv_bfloat16 Xs_lo[128][XS_STRIDE];
    __shared__ __align__(16) __nv_bfloat16 Ws_hi[128][XS_STRIDE];
    __shared__ __align__(16) __nv_bfloat16 Ws_lo[128][XS_STRIDE];

    const int tid = threadIdx.x;
    const int w   = tid >> 5;
    const int L   = tid & 31;
    const int m0  = blockIdx.x * 128;
    const int nt  = blockIdx.y;                   // 0:q 1:k 2:v
    float* outp = (nt == 0) ? g_q : (nt == 1) ? g_k : g_v;

    const __nv_bfloat16* whi = g_wt_hi + (size_t)nt * HSq * Dq;
    const __nv_bfloat16* wlo = g_wt_lo + (size_t)nt * HSq * Dq;

    const int mrow = (w & 3) * 32;     // warp m base within tile
    const int nbase = (w >> 2) * 64;   // warp n base within tile

    float c[2][8][4];
    #pragma unroll
    for (int mt = 0; mt < 2; mt++)
        #pragma unroll
        for (int j = 0; j < 8; j++)
            #pragma unroll
            for (int r = 0; r < 4; r++) c[mt][j][r] = 0.f;

    for (int ch = 0; ch < Dq / 32; ch++) {
        const int kb = ch * 32;
        __syncthreads();
        // Load X tile [128 x 32] fp32 -> split bf16
        #pragma unroll
        for (int i = 0; i < 4; i++) {
            int idx = tid + i * 256;
            int r = idx >> 3, c4 = idx & 7;
            float4 v = *(const float4*)&x[(size_t)(m0 + r) * Dq + kb + c4 * 4];
            uint32_t h0, l0, h1, l1;
            split2(v.x, v.y, h0, l0);
            split2(v.z, v.w, h1, l1);
            *(uint2*)&Xs_hi[r][c4 * 4] = make_uint2(h0, h1);
            *(uint2*)&Xs_lo[r][c4 * 4] = make_uint2(l0, l1);
        }
        // Load Wt tiles [128 x 32] bf16 hi/lo
        #pragma unroll
        for (int i = 0; i < 2; i++) {
            int idx = tid + i * 256;
            int r = idx >> 2, q = idx & 3;
            uint4 vh = *(const uint4*)&whi[(size_t)r * Dq + kb + q * 8];
            uint4 vl = *(const uint4*)&wlo[(size_t)r * Dq + kb + q * 8];
            *(uint4*)&Ws_hi[r][q * 8] = vh;
            *(uint4*)&Ws_lo[r][q * 8] = vl;
        }
        __syncthreads();

        #pragma unroll
        for (int ks = 0; ks < 2; ks++) {
            uint32_t ah[2][4], al[2][4];
            #pragma unroll
            for (int mt = 0; mt < 2; mt++)
                #pragma unroll
                for (int i = 0; i < 4; i++) {
                    int rr = mrow + mt * 16 + 8 * (i & 1) + (L >> 2);
                    int cc = ks * 16 + 8 * (i >> 1) + (L & 3) * 2;
                    ah[mt][i] = *(const uint32_t*)&Xs_hi[rr][cc];
                    al[mt][i] = *(const uint32_t*)&Xs_lo[rr][cc];
                }
            #pragma unroll
            for (int j = 0; j < 8; j++) {
                uint32_t bh[2], bl[2];
                int nr = nbase + 8 * j + (L >> 2);
                #pragma unroll
                for (int i = 0; i < 2; i++) {
                    int cc = ks * 16 + 8 * i + (L & 3) * 2;
                    bh[i] = *(const uint32_t*)&Ws_hi[nr][cc];
                    bl[i] = *(const uint32_t*)&Ws_lo[nr][cc];
                }
                #pragma unroll
                for (int mt = 0; mt < 2; mt++) {
                    mma_bf16(c[mt][j], ah[mt], bh);
                    mma_bf16(c[mt][j], al[mt], bh);
                    mma_bf16(c[mt][j], ah[mt], bl);
                }
            }
        }
    }

    // Epilogue: write fp32
    #pragma unroll
    for (int mt = 0; mt < 2; mt++) {
        int r0 = m0 + mrow + mt * 16 + (L >> 2);
        #pragma unroll
        for (int j = 0; j < 8; j++) {
            int cc = nbase + 8 * j + (L & 3) * 2;
            *(float2*)&outp[(size_t)r0 * HSq + cc]       = make_float2(c[mt][j][0], c[mt][j][1]);
            *(float2*)&outp[(size_t)(r0 + 8) * HSq + cc] = make_float2(c[mt][j][2], c[mt][j][3]);
        }
    }
}

// ---------------------------------------------------------------------------
// Kernel 2: causal flash attention with HMMA (split-bf16).
// Grid (16 pairs, 8 batch), block 128 (4 warps). BM=BN=64.
// Warp w owns q-rows 16w..16w+15. P never leaves registers.
// smem: K hi/lo + V hi/lo tiles [64][136] bf16 (stride 136 -> conflict-free ldsm).
// ---------------------------------------------------------------------------
#define KV_STRIDE 136                      // bf16 elems per row
#define KV_ROWB   (KV_STRIDE * 2)          // 272 bytes
#define KV_TILE_B (64 * KV_ROWB)           // 17408
#define OFF_KH 0
#define OFF_KL (OFF_KH + KV_TILE_B)
#define OFF_VH (OFF_KL + KV_TILE_B)
#define OFF_VL (OFF_VH + KV_TILE_B)
#define ATTN_SMEM (4 * KV_TILE_B)          // 69632

__global__ __launch_bounds__(128) void attn_mma_kernel(float* __restrict__ out)
{
    extern __shared__ char smc[];
    const uint32_t sb = smem_u32(smc);
    const int tid = threadIdx.x;
    const int w   = tid >> 5;
    const int L   = tid & 31;
    const int b   = blockIdx.y;
    const int pair = blockIdx.x;

    const float* qg = g_q + (size_t)b * Tq * HSq;
    const float* kg = g_k + (size_t)b * Tq * HSq;
    const float* vg = g_v + (size_t)b * Tq * HSq;

    const float scale = 0.08838834764831845f;  // 128^-0.5
    const int lr = L >> 2;                     // 0..7 row-in-frag
    const int lc = (L & 3) * 2;                // col pair base

    for (int half = 0; half < 2; half++) {
        const int qt = (half == 0) ? pair : (31 - pair);
        const int q0 = qt * 64;

        // Q fragments (scaled, split) in registers: 8 k-steps x 4 regs, hi/lo
        uint32_t qh[8][4], ql[8][4];
        #pragma unroll
        for (int s = 0; s < 8; s++)
            #pragma unroll
            for (int i = 0; i < 4; i++) {
                int rr = q0 + 16 * w + lr + 8 * (i & 1);
                int cc = 16 * s + lc + 8 * (i >> 1);
                float2 v = *(const float2*)&qg[(size_t)rr * HSq + cc];
                split2(v.x * scale, v.y * scale, qh[s][i], ql[s][i]);
            }

        float o[16][4];
        #pragma unroll
        for (int j = 0; j < 16; j++)
            #pragma unroll
            for (int r = 0; r < 4; r++) o[j][r] = 0.f;
        float m0v = -1e30f, m1v = -1e30f, l0v = 0.f, l1v = 0.f;

        const int ktiles = qt + 1;
        for (int kt = 0; kt < ktiles; kt++) {
            const int k0 = kt * 64;
            __syncthreads();
            // Load + split K, V tiles [64 x 128] fp32 -> smem bf16 hi/lo
            #pragma unroll
            for (int i = 0; i < 16; i++) {
                int idx = tid + i * 128;
                int r = idx >> 5, c4 = idx & 31;
                float4 kv = *(const float4*)&kg[(size_t)(k0 + r) * HSq + c4 * 4];
                uint32_t h0, l0, h1, l1;
                split2(kv.x, kv.y, h0, l0);
                split2(kv.z, kv.w, h1, l1);
                *(uint2*)(smc + OFF_KH + r * KV_ROWB + c4 * 8) = make_uint2(h0, h1);
                *(uint2*)(smc + OFF_KL + r * KV_ROWB + c4 * 8) = make_uint2(l0, l1);
                float4 vv = *(const float4*)&vg[(size_t)(k0 + r) * HSq + c4 * 4];
                split2(vv.x, vv.y, h0, l0);
                split2(vv.z, vv.w, h1, l1);
                *(uint2*)(smc + OFF_VH + r * KV_ROWB + c4 * 8) = make_uint2(h0, h1);
                *(uint2*)(smc + OFF_VL + r * KV_ROWB + c4 * 8) = make_uint2(l0, l1);
            }
            __syncthreads();

            // S = Q K^T : 8 n-tiles x 8 k-steps, 3-term split
            float c[8][4];
            #pragma unroll
            for (int j = 0; j < 8; j++) {
                c[j][0] = c[j][1] = c[j][2] = c[j][3] = 0.f;
                uint32_t kaddr = sb + (8 * j + (L & 7)) * KV_ROWB + (((L >> 3) & 1) ? 16 : 0);
                #pragma unroll
                for (int s = 0; s < 8; s++) {
                    uint32_t bh[2], bl[2];
                    ldsm_x2(bh[0], bh[1], kaddr + OFF_KH + 32 * s);
                    ldsm_x2(bl[0], bl[1], kaddr + OFF_KL + 32 * s);
                    mma_bf16(c[j], qh[s], bh);
                    mma_bf16(c[j], ql[s], bh);
                    mma_bf16(c[j], qh[s], bl);
                }
            }

            // Causal mask on diagonal tile
            if (kt == qt) {
                int r0 = 16 * w + lr, r1 = r0 + 8;
                #pragma unroll
                for (int j = 0; j < 8; j++) {
                    int n0 = 8 * j + lc;
                    if (n0 > r0)     c[j][0] = -1e30f;
                    if (n0 + 1 > r0) c[j][1] = -1e30f;
                    if (n0 > r1)     c[j][2] = -1e30f;
                    if (n0 + 1 > r1) c[j][3] = -1e30f;
                }
            }

            // Online softmax (rows r0 = regs 0,1 ; r1 = regs 2,3; 4-lane groups)
            float mx0 = -1e30f, mx1 = -1e30f;
            #pragma unroll
            for (int j = 0; j < 8; j++) {
                mx0 = fmaxf(mx0, fmaxf(c[j][0], c[j][1]));
                mx1 = fmaxf(mx1, fmaxf(c[j][2], c[j][3]));
            }
            #pragma unroll
            for (int off = 1; off <= 2; off <<= 1) {
                mx0 = fmaxf(mx0, __shfl_xor_sync(0xffffffffu, mx0, off));
                mx1 = fmaxf(mx1, __shfl_xor_sync(0xffffffffu, mx1, off));
            }
            float mn0 = fmaxf(m0v, mx0), mn1 = fmaxf(m1v, mx1);
            float a0 = __expf(m0v - mn0), a1 = __expf(m1v - mn1);
            float rs0 = 0.f, rs1 = 0.f;
            uint32_t phi[8][2], plo[8][2];
            #pragma unroll
            for (int j = 0; j < 8; j++) {
                float p0 = __expf(c[j][0] - mn0);
                float p1 = __expf(c[j][1] - mn0);
                float p2 = __expf(c[j][2] - mn1);
                float p3 = __expf(c[j][3] - mn1);
                rs0 += p0 + p1; rs1 += p2 + p3;
                split2(p0, p1, phi[j][0], plo[j][0]);
                split2(p2, p3, phi[j][1], plo[j][1]);
            }
            #pragma unroll
            for (int off = 1; off <= 2; off <<= 1) {
                rs0 += __shfl_xor_sync(0xffffffffu, rs0, off);
                rs1 += __shfl_xor_sync(0xffffffffu, rs1, off);
            }
            l0v = l0v * a0 + rs0;  m0v = mn0;
            l1v = l1v * a1 + rs1;  m1v = mn1;
            #pragma unroll
            for (int j = 0; j < 16; j++) {
                o[j][0] *= a0; o[j][1] *= a0;
                o[j][2] *= a1; o[j][3] *= a1;
            }

            // O += P V : 16 n-tiles x 4 k-steps (P hi/lo from regs, V hi/lo ldsm.trans)
            #pragma unroll
            for (int s = 0; s < 4; s++) {
                uint32_t ap[4] = { phi[2*s][0], phi[2*s][1], phi[2*s+1][0], phi[2*s+1][1] };
                uint32_t alo[4] = { plo[2*s][0], plo[2*s][1], plo[2*s+1][0], plo[2*s+1][1] };
                uint32_t vrow = sb + (16 * s + (L & 15)) * KV_ROWB;
                #pragma unroll
                for (int jj = 0; jj < 16; jj++) {
                    uint32_t bh[2], bl[2];
                    ldsm_x2_t(bh[0], bh[1], vrow + OFF_VH + 16 * jj);
                    ldsm_x2_t(bl[0], bl[1], vrow + OFF_VL + 16 * jj);
                    mma_bf16(o[jj], ap, bh);
                    mma_bf16(o[jj], alo, bh);
                    mma_bf16(o[jj], ap, bl);
                }
            }
        }

        // Epilogue: normalize + store
        float inv0 = __frcp_rn(l0v), inv1 = __frcp_rn(l1v);
        int r0 = q0 + 16 * w + lr;
        #pragma unroll
        for (int jj = 0; jj < 16; jj++) {
            int cc = 8 * jj + lc;
            *(float2*)&out[((size_t)b * Tq + r0) * HSq + cc] =
                make_float2(o[jj][0] * inv0, o[jj][1] * inv0);
            *(float2*)&out[((size_t)b * Tq + r0 + 8) * HSq + cc] =
                make_float2(o[jj][2] * inv1, o[jj][3] * inv1);
        }
    }
}

// ---------------------------------------------------------------------------
extern "C" void kernel_launch(void* const* d_in, const int* in_sizes, int n_in,
                              void* d_out, int out_size)
{
    const float* x  = (const float*)d_in[0];
    const float* Wq = (const float*)d_in[1];
    const float* Wk = (const float*)d_in[2];
    const float* Wv = (const float*)d_in[3];
    float* out = (float*)d_out;

    cudaFuncSetAttribute(attn_mma_kernel, cudaFuncAttributeMaxDynamicSharedMemorySize,
                         ATTN_SMEM);

    dim3 wgrid(Dq / 32, NTOT / 32);
    prep_w_kernel<<<wgrid, dim3(32, 8)>>>(Wq, Wk, Wv);

    dim3 pgrid(BT / 128, 3);
    proj_mma_kernel<<<pgrid, 256>>>(x);

    dim3 agrid(16, Bq);
    attn_mma_kernel<<<agrid, 128, ATTN_SMEM>>>(out);
}

// round 6
// speedup vs baseline: 2.5694x; 1.2150x over previous
#include <cuda_runtime.h>
#include <cuda_bf16.h>
#include <math.h>
#include <cstdint>

#define Bq   8
#define Tq   2048
#define Dq   1024
#define HSq  128
#define BT   (Bq * Tq)        // 16384 rows
#define NTOT 384              // 3 * HS

// Scratch (device globals — no allocs allowed). bf16 hi/lo split storage.
__device__ __align__(256) __nv_bfloat16 g_x_hi[BT * Dq];
__device__ __align__(256) __nv_bfloat16 g_x_lo[BT * Dq];
__device__ __align__(256) __nv_bfloat16 g_wt_hi[NTOT * Dq];   // W^T, K-major (Wq pre-scaled)
__device__ __align__(256) __nv_bfloat16 g_wt_lo[NTOT * Dq];
__device__ __align__(256) __nv_bfloat16 g_q_hi[BT * HSq];
__device__ __align__(256) __nv_bfloat16 g_q_lo[BT * HSq];
__device__ __align__(256) __nv_bfloat16 g_k_hi[BT * HSq];
__device__ __align__(256) __nv_bfloat16 g_k_lo[BT * HSq];
__device__ __align__(256) __nv_bfloat16 g_v_hi[BT * HSq];
__device__ __align__(256) __nv_bfloat16 g_v_lo[BT * HSq];

// ---------------------------------------------------------------------------
// Helpers
// ---------------------------------------------------------------------------
__device__ __forceinline__ void mma_bf16(float* c, const uint32_t* a, const uint32_t* b) {
    asm volatile(
        "mma.sync.aligned.m16n8k16.row.col.f32.bf16.bf16.f32 "
        "{%0,%1,%2,%3}, {%4,%5,%6,%7}, {%8,%9}, {%0,%1,%2,%3};"
        : "+f"(c[0]), "+f"(c[1]), "+f"(c[2]), "+f"(c[3])
        : "r"(a[0]), "r"(a[1]), "r"(a[2]), "r"(a[3]), "r"(b[0]), "r"(b[1]));
}
__device__ __forceinline__ void ldsm_x4(uint32_t* r, uint32_t addr) {
    asm volatile("ldmatrix.sync.aligned.m8n8.x4.shared.b16 {%0,%1,%2,%3}, [%4];"
                 : "=r"(r[0]), "=r"(r[1]), "=r"(r[2]), "=r"(r[3]) : "r"(addr));
}
__device__ __forceinline__ void ldsm_x4_t(uint32_t* r, uint32_t addr) {
    asm volatile("ldmatrix.sync.aligned.m8n8.x4.trans.shared.b16 {%0,%1,%2,%3}, [%4];"
                 : "=r"(r[0]), "=r"(r[1]), "=r"(r[2]), "=r"(r[3]) : "r"(addr));
}
__device__ __forceinline__ uint32_t smem_u32(const void* p) {
    uint32_t a;
    asm("{ .reg .u64 t; cvta.to.shared.u64 t, %1; cvt.u32.u64 %0, t; }"
        : "=r"(a) : "l"(p));
    return a;
}
__device__ __forceinline__ void cp16(uint32_t dst, const void* src) {
    asm volatile("cp.async.cg.shared.global [%0], [%1], 16;" :: "r"(dst), "l"(src));
}
#define CP_COMMIT() asm volatile("cp.async.commit_group;" ::: "memory")
#define CP_WAIT1()  asm volatile("cp.async.wait_group 1;" ::: "memory")

// split pair of floats into packed bf16 hi/lo
__device__ __forceinline__ void split2(float v0, float v1, uint32_t& hi, uint32_t& lo) {
    __nv_bfloat16 h0 = __float2bfloat16_rn(v0);
    __nv_bfloat16 h1 = __float2bfloat16_rn(v1);
    float l0 = v0 - __bfloat162float(h0);
    float l1 = v1 - __bfloat162float(h1);
    hi = (uint32_t)__bfloat16_as_ushort(h0) | ((uint32_t)__bfloat16_as_ushort(h1) << 16);
    __nv_bfloat16 g0 = __float2bfloat16_rn(l0);
    __nv_bfloat16 g1 = __float2bfloat16_rn(l1);
    lo = (uint32_t)__bfloat16_as_ushort(g0) | ((uint32_t)__bfloat16_as_ushort(g1) << 16);
}

// ---------------------------------------------------------------------------
// Kernel 0a: split x -> bf16 hi/lo. 8 floats per thread.
// ---------------------------------------------------------------------------
__global__ __launch_bounds__(256) void prep_x_kernel(const float* __restrict__ x)
{
    size_t i = ((size_t)blockIdx.x * 256 + threadIdx.x) * 8;
    float4 a = *(const float4*)&x[i];
    float4 b = *(const float4*)&x[i + 4];
    uint32_t h0, l0, h1, l1, h2, l2, h3, l3;
    split2(a.x, a.y, h0, l0); split2(a.z, a.w, h1, l1);
    split2(b.x, b.y, h2, l2); split2(b.z, b.w, h3, l3);
    *(uint4*)&g_x_hi[i] = make_uint4(h0, h1, h2, h3);
    *(uint4*)&g_x_lo[i] = make_uint4(l0, l1, l2, l3);
}

// ---------------------------------------------------------------------------
// Kernel 0b: transpose + split-convert weights (Wq scaled by 128^-0.5).
// ---------------------------------------------------------------------------
__global__ void prep_w_kernel(const float* __restrict__ Wq,
                              const float* __restrict__ Wk,
                              const float* __restrict__ Wv)
{
    __shared__ float t[32][33];
    const int k0 = blockIdx.x * 32;
    const int n0 = blockIdx.y * 32;
    const int slab = n0 >> 7;
    const float* W = (slab == 0) ? Wq : (slab == 1) ? Wk : Wv;
    const float sc = (slab == 0) ? 0.08838834764831845f : 1.0f;
    const int nn0 = n0 & 127;
    const int tx = threadIdx.x, ty = threadIdx.y;

    #pragma unroll
    for (int i = 0; i < 4; i++)
        t[ty * 4 + i][tx] = W[(size_t)(k0 + ty * 4 + i) * HSq + nn0 + tx] * sc;
    __syncthreads();
    #pragma unroll
    for (int i = 0; i < 4; i++) {
        int nr = ty * 4 + i;
        float v = t[tx][nr];
        __nv_bfloat16 hi = __float2bfloat16_rn(v);
        __nv_bfloat16 lo = __float2bfloat16_rn(v - __bfloat162float(hi));
        size_t o = (size_t)(n0 + nr) * Dq + k0 + tx;
        g_wt_hi[o] = hi;
        g_wt_lo[o] = lo;
    }
}

// ---------------------------------------------------------------------------
// Kernel 1: QKV projection, HMMA + cp.async double buffer.
// Grid (128 M-tiles, 3 slabs), block 256 (8 warps, 4x2). BM=128 BN=128 BK=32.
// Epilogue stores split bf16 hi/lo.
// ---------------------------------------------------------------------------
#define PS      80            // smem row pitch bytes (40 bf16)
#define P_ARR   (128 * PS)    // 10240
#define P_XH    0
#define P_XL    (1 * P_ARR)
#define P_WH    (2 * P_ARR)
#define P_WL    (3 * P_ARR)
#define P_BUF   (4 * P_ARR)   // 40960
#define PROJ_SMEM (2 * P_BUF) // 81920

__global__ __launch_bounds__(256) void proj_mma_kernel()
{
    extern __shared__ __align__(16) char smc[];
    const uint32_t sb = smem_u32(smc);
    const int tid = threadIdx.x;
    const int w   = tid >> 5;
    const int L   = tid & 31;
    const int m0  = blockIdx.x * 128;
    const int nt  = blockIdx.y;                   // 0:q 1:k 2:v
    __nv_bfloat16* out_hi = (nt == 0) ? g_q_hi : (nt == 1) ? g_k_hi : g_v_hi;
    __nv_bfloat16* out_lo = (nt == 0) ? g_q_lo : (nt == 1) ? g_k_lo : g_v_lo;

    const __nv_bfloat16* whi = g_wt_hi + (size_t)nt * HSq * Dq;
    const __nv_bfloat16* wlo = g_wt_lo + (size_t)nt * HSq * Dq;
    const __nv_bfloat16* xhi = g_x_hi + (size_t)m0 * Dq;
    const __nv_bfloat16* xlo = g_x_lo + (size_t)m0 * Dq;

    const int mrow  = (w & 3) * 32;
    const int nbase = (w >> 2) * 64;

    float c[2][8][4];
    #pragma unroll
    for (int mt = 0; mt < 2; mt++)
        #pragma unroll
        for (int j = 0; j < 8; j++)
            #pragma unroll
            for (int r = 0; r < 4; r++) c[mt][j][r] = 0.f;

    // prefetch helper (chunk ch into buffer bb)
    auto prefetch = [&](int ch, uint32_t bb) {
        const int kb = ch * 32;
        #pragma unroll
        for (int i = 0; i < 2; i++) {
            int idx = tid + i * 256;
            int r = idx >> 2, q = idx & 3;
            uint32_t d = bb + r * PS + q * 16;
            cp16(d + P_XH, xhi + (size_t)r * Dq + kb + q * 8);
            cp16(d + P_XL, xlo + (size_t)r * Dq + kb + q * 8);
            cp16(d + P_WH, whi + (size_t)r * Dq + kb + q * 8);
            cp16(d + P_WL, wlo + (size_t)r * Dq + kb + q * 8);
        }
    };

    prefetch(0, sb);
    CP_COMMIT();

    for (int ch = 0; ch < Dq / 32; ch++) {
        if (ch + 1 < Dq / 32) prefetch(ch + 1, sb + ((ch + 1) & 1) * P_BUF);
        CP_COMMIT();
        CP_WAIT1();
        __syncthreads();

        const char* bb = smc + (ch & 1) * P_BUF;
        #pragma unroll
        for (int ks = 0; ks < 2; ks++) {
            uint32_t ah[2][4], al[2][4];
            #pragma unroll
            for (int mt = 0; mt < 2; mt++)
                #pragma unroll
                for (int i = 0; i < 4; i++) {
                    int rr = mrow + mt * 16 + 8 * (i & 1) + (L >> 2);
                    int cc = ks * 16 + 8 * (i >> 1) + (L & 3) * 2;
                    ah[mt][i] = *(const uint32_t*)(bb + P_XH + rr * PS + cc * 2);
                    al[mt][i] = *(const uint32_t*)(bb + P_XL + rr * PS + cc * 2);
                }
            #pragma unroll
            for (int j = 0; j < 8; j++) {
                uint32_t bh[2], bl[2];
                int nr = nbase + 8 * j + (L >> 2);
                #pragma unroll
                for (int i = 0; i < 2; i++) {
                    int cc = ks * 16 + 8 * i + (L & 3) * 2;
                    bh[i] = *(const uint32_t*)(bb + P_WH + nr * PS + cc * 2);
                    bl[i] = *(const uint32_t*)(bb + P_WL + nr * PS + cc * 2);
                }
                #pragma unroll
                for (int mt = 0; mt < 2; mt++) {
                    mma_bf16(c[mt][j], ah[mt], bh);
                    mma_bf16(c[mt][j], al[mt], bh);
                    mma_bf16(c[mt][j], ah[mt], bl);
                }
            }
        }
        __syncthreads();
    }

    // Epilogue: split fp32 accum -> bf16 hi/lo stores
    #pragma unroll
    for (int mt = 0; mt < 2; mt++) {
        int r0 = m0 + mrow + mt * 16 + (L >> 2);
        #pragma unroll
        for (int j = 0; j < 8; j++) {
            int cc = nbase + 8 * j + (L & 3) * 2;
            uint32_t h, l;
            split2(c[mt][j][0], c[mt][j][1], h, l);
            *(uint32_t*)&out_hi[(size_t)r0 * HSq + cc] = h;
            *(uint32_t*)&out_lo[(size_t)r0 * HSq + cc] = l;
            split2(c[mt][j][2], c[mt][j][3], h, l);
            *(uint32_t*)&out_hi[(size_t)(r0 + 8) * HSq + cc] = h;
            *(uint32_t*)&out_lo[(size_t)(r0 + 8) * HSq + cc] = l;
        }
    }
}

// ---------------------------------------------------------------------------
// Kernel 2: causal flash attention, HMMA + cp.async double buffer + ldsm.x4.
// Grid (16 pairs, 8 batch), block 128 (4 warps). BM=BN=64.
// ---------------------------------------------------------------------------
#define KV_ROWB 272                        // 128 bf16 data + 8 pad
#define KV_TILE_B (64 * KV_ROWB)           // 17408
#define A_KH 0
#define A_KL (1 * KV_TILE_B)
#define A_VH (2 * KV_TILE_B)
#define A_VL (3 * KV_TILE_B)
#define A_BUF (4 * KV_TILE_B)              // 69632
#define ATTN_SMEM (2 * A_BUF)              // 139264

__global__ __launch_bounds__(128) void attn_mma_kernel(float* __restrict__ out)
{
    extern __shared__ __align__(16) char smc[];
    const uint32_t sb = smem_u32(smc);
    const int tid = threadIdx.x;
    const int w   = tid >> 5;
    const int L   = tid & 31;
    const int b   = blockIdx.y;
    const int pair = blockIdx.x;

    const __nv_bfloat16* qh_g = g_q_hi + (size_t)b * Tq * HSq;
    const __nv_bfloat16* ql_g = g_q_lo + (size_t)b * Tq * HSq;
    const __nv_bfloat16* kh_g = g_k_hi + (size_t)b * Tq * HSq;
    const __nv_bfloat16* kl_g = g_k_lo + (size_t)b * Tq * HSq;
    const __nv_bfloat16* vh_g = g_v_hi + (size_t)b * Tq * HSq;
    const __nv_bfloat16* vl_g = g_v_lo + (size_t)b * Tq * HSq;

    const int lr = L >> 2;
    const int lc = (L & 3) * 2;

    auto prefetch = [&](int k0, uint32_t bb) {
        #pragma unroll
        for (int i = 0; i < 8; i++) {
            int idx = tid + i * 128;
            int r = idx >> 4, q = idx & 15;
            uint32_t d = bb + r * KV_ROWB + q * 16;
            size_t so = (size_t)(k0 + r) * HSq + q * 8;
            cp16(d + A_KH, kh_g + so);
            cp16(d + A_KL, kl_g + so);
            cp16(d + A_VH, vh_g + so);
            cp16(d + A_VL, vl_g + so);
        }
    };

    for (int half = 0; half < 2; half++) {
        const int qt = (half == 0) ? pair : (31 - pair);
        const int q0 = qt * 64;

        // Q fragments (pre-scaled, pre-split) straight from gmem
        uint32_t qh[8][4], ql[8][4];
        #pragma unroll
        for (int s = 0; s < 8; s++)
            #pragma unroll
            for (int i = 0; i < 4; i++) {
                int rr = q0 + 16 * w + lr + 8 * (i & 1);
                int cc = 16 * s + lc + 8 * (i >> 1);
                qh[s][i] = *(const uint32_t*)&qh_g[(size_t)rr * HSq + cc];
                ql[s][i] = *(const uint32_t*)&ql_g[(size_t)rr * HSq + cc];
            }

        float o[16][4];
        #pragma unroll
        for (int j = 0; j < 16; j++)
            #pragma unroll
            for (int r = 0; r < 4; r++) o[j][r] = 0.f;
        float m0v = -1e30f, m1v = -1e30f, l0v = 0.f, l1v = 0.f;

        const int ktiles = qt + 1;

        prefetch(0, sb);
        CP_COMMIT();

        for (int kt = 0; kt < ktiles; kt++) {
            if (kt + 1 < ktiles) prefetch((kt + 1) * 64, sb + ((kt + 1) & 1) * A_BUF);
            CP_COMMIT();
            CP_WAIT1();
            __syncthreads();

            const uint32_t bb = sb + (kt & 1) * A_BUF;

            // S = Q K^T : 8 n-tiles x 4 k-step-pairs (ldsm.x4), 3-term split
            float c[8][4];
            #pragma unroll
            for (int j = 0; j < 8; j++) {
                c[j][0] = c[j][1] = c[j][2] = c[j][3] = 0.f;
                uint32_t rowaddr = bb + (8 * j + (L & 7)) * KV_ROWB + ((L >> 3) & 3) * 16;
                #pragma unroll
                for (int sp = 0; sp < 4; sp++) {
                    uint32_t bh[4], bl[4];
                    ldsm_x4(bh, rowaddr + A_KH + 64 * sp);
                    ldsm_x4(bl, rowaddr + A_KL + 64 * sp);
                    mma_bf16(c[j], qh[2 * sp],     bh);
                    mma_bf16(c[j], ql[2 * sp],     bh);
                    mma_bf16(c[j], qh[2 * sp],     bl);
                    mma_bf16(c[j], qh[2 * sp + 1], bh + 2);
                    mma_bf16(c[j], ql[2 * sp + 1], bh + 2);
                    mma_bf16(c[j], qh[2 * sp + 1], bl + 2);
                }
            }

            // Causal mask on diagonal tile
            if (kt == qt) {
                int r0 = 16 * w + lr, r1 = r0 + 8;
                #pragma unroll
                for (int j = 0; j < 8; j++) {
                    int n0 = 8 * j + lc;
                    if (n0 > r0)     c[j][0] = -1e30f;
                    if (n0 + 1 > r0) c[j][1] = -1e30f;
                    if (n0 > r1)     c[j][2] = -1e30f;
                    if (n0 + 1 > r1) c[j][3] = -1e30f;
                }
            }

            // Online softmax
            float mx0 = -1e30f, mx1 = -1e30f;
            #pragma unroll
            for (int j = 0; j < 8; j++) {
                mx0 = fmaxf(mx0, fmaxf(c[j][0], c[j][1]));
                mx1 = fmaxf(mx1, fmaxf(c[j][2], c[j][3]));
            }
            #pragma unroll
            for (int off = 1; off <= 2; off <<= 1) {
                mx0 = fmaxf(mx0, __shfl_xor_sync(0xffffffffu, mx0, off));
                mx1 = fmaxf(mx1, __shfl_xor_sync(0xffffffffu, mx1, off));
            }
            float mn0 = fmaxf(m0v, mx0), mn1 = fmaxf(m1v, mx1);
            float a0 = __expf(m0v - mn0), a1 = __expf(m1v - mn1);
            float rs0 = 0.f, rs1 = 0.f;
            uint32_t phi[8][2], plo[8][2];
            #pragma unroll
            for (int j = 0; j < 8; j++) {
                float p0 = __expf(c[j][0] - mn0);
                float p1 = __expf(c[j][1] - mn0);
                float p2 = __expf(c[j][2] - mn1);
                float p3 = __expf(c[j][3] - mn1);
                rs0 += p0 + p1; rs1 += p2 + p3;
                split2(p0, p1, phi[j][0], plo[j][0]);
                split2(p2, p3, phi[j][1], plo[j][1]);
            }
            #pragma unroll
            for (int off = 1; off <= 2; off <<= 1) {
                rs0 += __shfl_xor_sync(0xffffffffu, rs0, off);
                rs1 += __shfl_xor_sync(0xffffffffu, rs1, off);
            }
            l0v = l0v * a0 + rs0;  m0v = mn0;
            l1v = l1v * a1 + rs1;  m1v = mn1;
            #pragma unroll
            for (int j = 0; j < 16; j++) {
                o[j][0] *= a0; o[j][1] *= a0;
                o[j][2] *= a1; o[j][3] *= a1;
            }

            // O += P V : ldsm.x4.trans loads two n-tiles at once
            #pragma unroll
            for (int s = 0; s < 4; s++) {
                uint32_t ap[4]  = { phi[2*s][0], phi[2*s][1], phi[2*s+1][0], phi[2*s+1][1] };
                uint32_t alo[4] = { plo[2*s][0], plo[2*s][1], plo[2*s+1][0], plo[2*s+1][1] };
                uint32_t vaddr = bb + (16 * s + (L & 15)) * KV_ROWB + (L >> 4) * 16;
                #pragma unroll
                for (int jj = 0; jj < 16; jj += 2) {
                    uint32_t bh[4], bl[4];
                    ldsm_x4_t(bh, vaddr + A_VH + 16 * jj);
                    ldsm_x4_t(bl, vaddr + A_VL + 16 * jj);
                    mma_bf16(o[jj],     ap,  bh);
                    mma_bf16(o[jj],     alo, bh);
                    mma_bf16(o[jj],     ap,  bl);
                    mma_bf16(o[jj + 1], ap,  bh + 2);
                    mma_bf16(o[jj + 1], alo, bh + 2);
                    mma_bf16(o[jj + 1], ap,  bl + 2);
                }
            }
            __syncthreads();
        }

        // Epilogue: normalize + store fp32
        float inv0 = __frcp_rn(l0v), inv1 = __frcp_rn(l1v);
        int r0 = q0 + 16 * w + lr;
        #pragma unroll
        for (int jj = 0; jj < 16; jj++) {
            int cc = 8 * jj + lc;
            *(float2*)&out[((size_t)b * Tq + r0) * HSq + cc] =
                make_float2(o[jj][0] * inv0, o[jj][1] * inv0);
            *(float2*)&out[((size_t)b * Tq + r0 + 8) * HSq + cc] =
                make_float2(o[jj][2] * inv1, o[jj][3] * inv1);
        }
    }
}

// ---------------------------------------------------------------------------
extern "C" void kernel_launch(void* const* d_in, const int* in_sizes, int n_in,
                              void* d_out, int out_size)
{
    const float* x  = (const float*)d_in[0];
    const float* Wq = (const float*)d_in[1];
    const float* Wk = (const float*)d_in[2];
    const float* Wv = (const float*)d_in[3];
    float* out = (float*)d_out;

    cudaFuncSetAttribute(proj_mma_kernel, cudaFuncAttributeMaxDynamicSharedMemorySize,
                         PROJ_SMEM);
    cudaFuncSetAttribute(attn_mma_kernel, cudaFuncAttributeMaxDynamicSharedMemorySize,
                         ATTN_SMEM);

    prep_x_kernel<<<BT * Dq / (256 * 8), 256>>>(x);

    dim3 wgrid(Dq / 32, NTOT / 32);
    prep_w_kernel<<<wgrid, dim3(32, 8)>>>(Wq, Wk, Wv);

    dim3 pgrid(BT / 128, 3);
    proj_mma_kernel<<<pgrid, 256, PROJ_SMEM>>>();

    dim3 agrid(16, Bq);
    attn_mma_kernel<<<agrid, 128, ATTN_SMEM>>>(out);
}

// round 7
// speedup vs baseline: 2.6435x; 1.0288x over previous
#include <cuda_runtime.h>
#include <cuda_bf16.h>
#include <math.h>
#include <cstdint>

#define Bq   8
#define Tq   2048
#define Dq   1024
#define HSq  128
#define BT   (Bq * Tq)        // 16384 rows
#define NTOT 384              // 3 * HS

// Scratch (device globals — no allocs allowed). bf16 hi/lo split storage.
__device__ __align__(256) __nv_bfloat16 g_x_hi[BT * Dq];
__device__ __align__(256) __nv_bfloat16 g_x_lo[BT * Dq];
__device__ __align__(256) __nv_bfloat16 g_wt_hi[NTOT * Dq];   // W^T, K-major (Wq pre-scaled)
__device__ __align__(256) __nv_bfloat16 g_wt_lo[NTOT * Dq];
__device__ __align__(256) __nv_bfloat16 g_q_hi[BT * HSq];
__device__ __align__(256) __nv_bfloat16 g_q_lo[BT * HSq];
__device__ __align__(256) __nv_bfloat16 g_k_hi[BT * HSq];
__device__ __align__(256) __nv_bfloat16 g_k_lo[BT * HSq];
__device__ __align__(256) __nv_bfloat16 g_v_hi[BT * HSq];
__device__ __align__(256) __nv_bfloat16 g_v_lo[BT * HSq];

// ---------------------------------------------------------------------------
// Helpers
// ---------------------------------------------------------------------------
__device__ __forceinline__ void mma_bf16(float* c, const uint32_t* a, const uint32_t* b) {
    asm volatile(
        "mma.sync.aligned.m16n8k16.row.col.f32.bf16.bf16.f32 "
        "{%0,%1,%2,%3}, {%4,%5,%6,%7}, {%8,%9}, {%0,%1,%2,%3};"
        : "+f"(c[0]), "+f"(c[1]), "+f"(c[2]), "+f"(c[3])
        : "r"(a[0]), "r"(a[1]), "r"(a[2]), "r"(a[3]), "r"(b[0]), "r"(b[1]));
}
__device__ __forceinline__ void ldsm_x4(uint32_t* r, uint32_t addr) {
    asm volatile("ldmatrix.sync.aligned.m8n8.x4.shared.b16 {%0,%1,%2,%3}, [%4];"
                 : "=r"(r[0]), "=r"(r[1]), "=r"(r[2]), "=r"(r[3]) : "r"(addr));
}
__device__ __forceinline__ void ldsm_x4_t(uint32_t* r, uint32_t addr) {
    asm volatile("ldmatrix.sync.aligned.m8n8.x4.trans.shared.b16 {%0,%1,%2,%3}, [%4];"
                 : "=r"(r[0]), "=r"(r[1]), "=r"(r[2]), "=r"(r[3]) : "r"(addr));
}
__device__ __forceinline__ uint32_t smem_u32(const void* p) {
    uint32_t a;
    asm("{ .reg .u64 t; cvta.to.shared.u64 t, %1; cvt.u32.u64 %0, t; }"
        : "=r"(a) : "l"(p));
    return a;
}
__device__ __forceinline__ void cp16(uint32_t dst, const void* src) {
    asm volatile("cp.async.cg.shared.global [%0], [%1], 16;" :: "r"(dst), "l"(src));
}
#define CP_COMMIT() asm volatile("cp.async.commit_group;" ::: "memory")
#define CP_WAIT0()  asm volatile("cp.async.wait_group 0;" ::: "memory")
#define CP_WAIT1()  asm volatile("cp.async.wait_group 1;" ::: "memory")

// split pair of floats into packed bf16 hi/lo
__device__ __forceinline__ void split2(float v0, float v1, uint32_t& hi, uint32_t& lo) {
    __nv_bfloat16 h0 = __float2bfloat16_rn(v0);
    __nv_bfloat16 h1 = __float2bfloat16_rn(v1);
    float l0 = v0 - __bfloat162float(h0);
    float l1 = v1 - __bfloat162float(h1);
    hi = (uint32_t)__bfloat16_as_ushort(h0) | ((uint32_t)__bfloat16_as_ushort(h1) << 16);
    __nv_bfloat16 g0 = __float2bfloat16_rn(l0);
    __nv_bfloat16 g1 = __float2bfloat16_rn(l1);
    lo = (uint32_t)__bfloat16_as_ushort(g0) | ((uint32_t)__bfloat16_as_ushort(g1) << 16);
}

// ---------------------------------------------------------------------------
// Kernel 0a: split x -> bf16 hi/lo. 8 floats per thread.
// ---------------------------------------------------------------------------
__global__ __launch_bounds__(256) void prep_x_kernel(const float* __restrict__ x)
{
    size_t i = ((size_t)blockIdx.x * 256 + threadIdx.x) * 8;
    float4 a = *(const float4*)&x[i];
    float4 b = *(const float4*)&x[i + 4];
    uint32_t h0, l0, h1, l1, h2, l2, h3, l3;
    split2(a.x, a.y, h0, l0); split2(a.z, a.w, h1, l1);
    split2(b.x, b.y, h2, l2); split2(b.z, b.w, h3, l3);
    *(uint4*)&g_x_hi[i] = make_uint4(h0, h1, h2, h3);
    *(uint4*)&g_x_lo[i] = make_uint4(l0, l1, l2, l3);
}

// ---------------------------------------------------------------------------
// Kernel 0b: transpose + split-convert weights (Wq scaled by 128^-0.5).
// ---------------------------------------------------------------------------
__global__ void prep_w_kernel(const float* __restrict__ Wq,
                              const float* __restrict__ Wk,
                              const float* __restrict__ Wv)
{
    __shared__ float t[32][33];
    const int k0 = blockIdx.x * 32;
    const int n0 = blockIdx.y * 32;
    const int slab = n0 >> 7;
    const float* W = (slab == 0) ? Wq : (slab == 1) ? Wk : Wv;
    const float sc = (slab == 0) ? 0.08838834764831845f : 1.0f;
    const int nn0 = n0 & 127;
    const int tx = threadIdx.x, ty = threadIdx.y;

    #pragma unroll
    for (int i = 0; i < 4; i++)
        t[ty * 4 + i][tx] = W[(size_t)(k0 + ty * 4 + i) * HSq + nn0 + tx] * sc;
    __syncthreads();
    #pragma unroll
    for (int i = 0; i < 4; i++) {
        int nr = ty * 4 + i;
        float v = t[tx][nr];
        __nv_bfloat16 hi = __float2bfloat16_rn(v);
        __nv_bfloat16 lo = __float2bfloat16_rn(v - __bfloat162float(hi));
        size_t o = (size_t)(n0 + nr) * Dq + k0 + tx;
        g_wt_hi[o] = hi;
        g_wt_lo[o] = lo;
    }
}

// ---------------------------------------------------------------------------
// Kernel 1: QKV projection, HMMA + cp.async double buffer + ldmatrix frags.
// Grid (128 M-tiles, 3 slabs), block 256 (8 warps, 4x2). BM=128 BN=128 BK=32.
// ---------------------------------------------------------------------------
#define PS      80            // smem row pitch bytes (40 bf16)
#define P_ARR   (128 * PS)    // 10240
#define P_XH    0
#define P_XL    (1 * P_ARR)
#define P_WH    (2 * P_ARR)
#define P_WL    (3 * P_ARR)
#define P_BUF   (4 * P_ARR)   // 40960
#define PROJ_SMEM (2 * P_BUF) // 81920

__global__ __launch_bounds__(256, 2) void proj_mma_kernel()
{
    extern __shared__ __align__(16) char smc[];
    const uint32_t sb = smem_u32(smc);
    const int tid = threadIdx.x;
    const int w   = tid >> 5;
    const int L   = tid & 31;
    const int m0  = blockIdx.x * 128;
    const int nt  = blockIdx.y;                   // 0:q 1:k 2:v
    __nv_bfloat16* out_hi = (nt == 0) ? g_q_hi : (nt == 1) ? g_k_hi : g_v_hi;
    __nv_bfloat16* out_lo = (nt == 0) ? g_q_lo : (nt == 1) ? g_k_lo : g_v_lo;

    const __nv_bfloat16* whi = g_wt_hi + (size_t)nt * HSq * Dq;
    const __nv_bfloat16* wlo = g_wt_lo + (size_t)nt * HSq * Dq;
    const __nv_bfloat16* xhi = g_x_hi + (size_t)m0 * Dq;
    const __nv_bfloat16* xlo = g_x_lo + (size_t)m0 * Dq;

    const int mrow  = (w & 3) * 32;
    const int nbase = (w >> 2) * 64;

    float c[2][8][4];
    #pragma unroll
    for (int mt = 0; mt < 2; mt++)
        #pragma unroll
        for (int j = 0; j < 8; j++)
            #pragma unroll
            for (int r = 0; r < 4; r++) c[mt][j][r] = 0.f;

    auto prefetch = [&](int ch, uint32_t bb) {
        const int kb = ch * 32;
        #pragma unroll
        for (int i = 0; i < 2; i++) {
            int idx = tid + i * 256;
            int r = idx >> 2, q = idx & 3;
            uint32_t d = bb + r * PS + q * 16;
            cp16(d + P_XH, xhi + (size_t)r * Dq + kb + q * 8);
            cp16(d + P_XL, xlo + (size_t)r * Dq + kb + q * 8);
            cp16(d + P_WH, whi + (size_t)r * Dq + kb + q * 8);
            cp16(d + P_WL, wlo + (size_t)r * Dq + kb + q * 8);
        }
    };

    prefetch(0, sb);
    CP_COMMIT();

    for (int ch = 0; ch < Dq / 32; ch++) {
        if (ch + 1 < Dq / 32) prefetch(ch + 1, sb + ((ch + 1) & 1) * P_BUF);
        CP_COMMIT();
        CP_WAIT1();
        __syncthreads();

        const uint32_t base = sb + (ch & 1) * P_BUF;

        // A fragments: ldmatrix.x4, [mt][ks][4] for hi and lo
        uint32_t ah[2][2][4], al[2][2][4];
        #pragma unroll
        for (int mt = 0; mt < 2; mt++) {
            uint32_t arow = base + P_XH
                + (uint32_t)(mrow + mt * 16 + (L & 7) + ((L >> 3) & 1) * 8) * PS
                + (L >> 4) * 16;
            #pragma unroll
            for (int ks = 0; ks < 2; ks++) {
                ldsm_x4(ah[mt][ks], arow + ks * 32);
                ldsm_x4(al[mt][ks], arow + ks * 32 + (P_XL - P_XH));
            }
        }

        #pragma unroll
        for (int j = 0; j < 8; j++) {
            uint32_t brow = base + P_WH
                + (uint32_t)(nbase + 8 * j + (L & 7)) * PS + ((L >> 3) & 3) * 16;
            uint32_t bh[4], bl[4];
            ldsm_x4(bh, brow);
            ldsm_x4(bl, brow + (P_WL - P_WH));
            #pragma unroll
            for (int ks = 0; ks < 2; ks++) {
                #pragma unroll
                for (int mt = 0; mt < 2; mt++) {
                    mma_bf16(c[mt][j], ah[mt][ks], bh + 2 * ks);
                    mma_bf16(c[mt][j], al[mt][ks], bh + 2 * ks);
                    mma_bf16(c[mt][j], ah[mt][ks], bl + 2 * ks);
                }
            }
        }
        __syncthreads();
    }

    // Epilogue: split fp32 accum -> bf16 hi/lo stores
    #pragma unroll
    for (int mt = 0; mt < 2; mt++) {
        int r0 = m0 + mrow + mt * 16 + (L >> 2);
        #pragma unroll
        for (int j = 0; j < 8; j++) {
            int cc = nbase + 8 * j + (L & 3) * 2;
            uint32_t h, l;
            split2(c[mt][j][0], c[mt][j][1], h, l);
            *(uint32_t*)&out_hi[(size_t)r0 * HSq + cc] = h;
            *(uint32_t*)&out_lo[(size_t)r0 * HSq + cc] = l;
            split2(c[mt][j][2], c[mt][j][3], h, l);
            *(uint32_t*)&out_hi[(size_t)(r0 + 8) * HSq + cc] = h;
            *(uint32_t*)&out_lo[(size_t)(r0 + 8) * HSq + cc] = l;
        }
    }
}

// ---------------------------------------------------------------------------
// Kernel 2: causal flash attention, HMMA. K double-buffered, V single-buffered
// -> smem 104448 -> 2 CTAs/SM (8 warps). Grid (16 pairs, 8 batch), block 128.
// ---------------------------------------------------------------------------
#define KV_ROWB 272                        // 128 bf16 data + 8 pad
#define KTILE   (64 * KV_ROWB)             // 17408
#define A_KH0   0
#define A_KL0   (1 * KTILE)
#define A_KH1   (2 * KTILE)
#define A_KL1   (3 * KTILE)
#define A_VH    (4 * KTILE)
#define A_VL    (5 * KTILE)
#define ATTN_SMEM (6 * KTILE)              // 104448

__global__ __launch_bounds__(128, 2) void attn_mma_kernel(float* __restrict__ out)
{
    extern __shared__ __align__(16) char smc[];
    const uint32_t sb = smem_u32(smc);
    const int tid = threadIdx.x;
    const int w   = tid >> 5;
    const int L   = tid & 31;
    const int b   = blockIdx.y;
    const int pair = blockIdx.x;

    const __nv_bfloat16* qh_g = g_q_hi + (size_t)b * Tq * HSq;
    const __nv_bfloat16* ql_g = g_q_lo + (size_t)b * Tq * HSq;
    const __nv_bfloat16* kh_g = g_k_hi + (size_t)b * Tq * HSq;
    const __nv_bfloat16* kl_g = g_k_lo + (size_t)b * Tq * HSq;
    const __nv_bfloat16* vh_g = g_v_hi + (size_t)b * Tq * HSq;
    const __nv_bfloat16* vl_g = g_v_lo + (size_t)b * Tq * HSq;

    const int lr = L >> 2;
    const int lc = (L & 3) * 2;

    auto prefetch_k = [&](int k0, int buf) {
        uint32_t kh = sb + (buf ? A_KH1 : A_KH0);
        uint32_t kl = sb + (buf ? A_KL1 : A_KL0);
        #pragma unroll
        for (int i = 0; i < 8; i++) {
            int idx = tid + i * 128;
            int r = idx >> 4, q = idx & 15;
            uint32_t d = r * KV_ROWB + q * 16;
            size_t so = (size_t)(k0 + r) * HSq + q * 8;
            cp16(kh + d, kh_g + so);
            cp16(kl + d, kl_g + so);
        }
    };
    auto prefetch_v = [&](int k0) {
        #pragma unroll
        for (int i = 0; i < 8; i++) {
            int idx = tid + i * 128;
            int r = idx >> 4, q = idx & 15;
            uint32_t d = r * KV_ROWB + q * 16;
            size_t so = (size_t)(k0 + r) * HSq + q * 8;
            cp16(sb + A_VH + d, vh_g + so);
            cp16(sb + A_VL + d, vl_g + so);
        }
    };

    for (int half = 0; half < 2; half++) {
        const int qt = (half == 0) ? pair : (31 - pair);
        const int q0 = qt * 64;

        // Q fragments (pre-scaled, pre-split) straight from gmem
        uint32_t qh[8][4], ql[8][4];
        #pragma unroll
        for (int s = 0; s < 8; s++)
            #pragma unroll
            for (int i = 0; i < 4; i++) {
                int rr = q0 + 16 * w + lr + 8 * (i & 1);
                int cc = 16 * s + lc + 8 * (i >> 1);
                qh[s][i] = *(const uint32_t*)&qh_g[(size_t)rr * HSq + cc];
                ql[s][i] = *(const uint32_t*)&ql_g[(size_t)rr * HSq + cc];
            }

        float o[16][4];
        #pragma unroll
        for (int j = 0; j < 16; j++)
            #pragma unroll
            for (int r = 0; r < 4; r++) o[j][r] = 0.f;
        float m0v = -1e30f, m1v = -1e30f, l0v = 0.f, l1v = 0.f;

        const int ktiles = qt + 1;

        prefetch_k(0, 0); CP_COMMIT();
        prefetch_v(0);    CP_COMMIT();

        for (int kt = 0; kt < ktiles; kt++) {
            CP_WAIT1();           // K(kt) complete (V(kt)/K(kt+1) may pend)
            __syncthreads();
            if (kt + 1 < ktiles) { prefetch_k((kt + 1) * 64, (kt + 1) & 1); CP_COMMIT(); }

            const uint32_t kb_hi = sb + ((kt & 1) ? A_KH1 : A_KH0);

            // S = Q K^T : 8 n-tiles x 4 k-step-pairs (ldsm.x4), 3-term split
            float c[8][4];
            #pragma unroll
            for (int j = 0; j < 8; j++) {
                c[j][0] = c[j][1] = c[j][2] = c[j][3] = 0.f;
                uint32_t rowaddr = kb_hi + (8 * j + (L & 7)) * KV_ROWB + ((L >> 3) & 3) * 16;
                #pragma unroll
                for (int sp = 0; sp < 4; sp++) {
                    uint32_t bh[4], bl[4];
                    ldsm_x4(bh, rowaddr + 64 * sp);
                    ldsm_x4(bl, rowaddr + 64 * sp + KTILE);
                    mma_bf16(c[j], qh[2 * sp],     bh);
                    mma_bf16(c[j], ql[2 * sp],     bh);
                    mma_bf16(c[j], qh[2 * sp],     bl);
                    mma_bf16(c[j], qh[2 * sp + 1], bh + 2);
                    mma_bf16(c[j], ql[2 * sp + 1], bh + 2);
                    mma_bf16(c[j], qh[2 * sp + 1], bl + 2);
                }
            }

            // Causal mask on diagonal tile
            if (kt == qt) {
                int r0 = 16 * w + lr, r1 = r0 + 8;
                #pragma unroll
                for (int j = 0; j < 8; j++) {
                    int n0 = 8 * j + lc;
                    if (n0 > r0)     c[j][0] = -1e30f;
                    if (n0 + 1 > r0) c[j][1] = -1e30f;
                    if (n0 > r1)     c[j][2] = -1e30f;
                    if (n0 + 1 > r1) c[j][3] = -1e30f;
                }
            }

            // Online softmax
            float mx0 = -1e30f, mx1 = -1e30f;
            #pragma unroll
            for (int j = 0; j < 8; j++) {
                mx0 = fmaxf(mx0, fmaxf(c[j][0], c[j][1]));
                mx1 = fmaxf(mx1, fmaxf(c[j][2], c[j][3]));
            }
            #pragma unroll
            for (int off = 1; off <= 2; off <<= 1) {
                mx0 = fmaxf(mx0, __shfl_xor_sync(0xffffffffu, mx0, off));
                mx1 = fmaxf(mx1, __shfl_xor_sync(0xffffffffu, mx1, off));
            }
            float mn0 = fmaxf(m0v, mx0), mn1 = fmaxf(m1v, mx1);
            float a0 = __expf(m0v - mn0), a1 = __expf(m1v - mn1);
            float rs0 = 0.f, rs1 = 0.f;
            uint32_t phi[8][2], plo[8][2];
            #pragma unroll
            for (int j = 0; j < 8; j++) {
                float p0 = __expf(c[j][0] - mn0);
                float p1 = __expf(c[j][1] - mn0);
                float p2 = __expf(c[j][2] - mn1);
                float p3 = __expf(c[j][3] - mn1);
                rs0 += p0 + p1; rs1 += p2 + p3;
                split2(p0, p1, phi[j][0], plo[j][0]);
                split2(p2, p3, phi[j][1], plo[j][1]);
            }
            #pragma unroll
            for (int off = 1; off <= 2; off <<= 1) {
                rs0 += __shfl_xor_sync(0xffffffffu, rs0, off);
                rs1 += __shfl_xor_sync(0xffffffffu, rs1, off);
            }
            l0v = l0v * a0 + rs0;  m0v = mn0;
            l1v = l1v * a1 + rs1;  m1v = mn1;
            #pragma unroll
            for (int j = 0; j < 16; j++) {
                o[j][0] *= a0; o[j][1] *= a0;
                o[j][2] *= a1; o[j][3] *= a1;
            }

            // Wait for V(kt); then barrier so all threads' copies are visible
            if (kt + 1 < ktiles) { CP_WAIT1(); } else { CP_WAIT0(); }
            __syncthreads();

            // O += P V : ldsm.x4.trans loads two n-tiles at once
            #pragma unroll
            for (int s = 0; s < 4; s++) {
                uint32_t ap[4]  = { phi[2*s][0], phi[2*s][1], phi[2*s+1][0], phi[2*s+1][1] };
                uint32_t alo[4] = { plo[2*s][0], plo[2*s][1], plo[2*s+1][0], plo[2*s+1][1] };
                uint32_t vaddr = sb + A_VH + (16 * s + (L & 15)) * KV_ROWB + (L >> 4) * 16;
                #pragma unroll
                for (int jj = 0; jj < 16; jj += 2) {
                    uint32_t bh[4], bl[4];
                    ldsm_x4_t(bh, vaddr + 16 * jj);
                    ldsm_x4_t(bl, vaddr + 16 * jj + KTILE);
                    mma_bf16(o[jj],     ap,  bh);
                    mma_bf16(o[jj],     alo, bh);
                    mma_bf16(o[jj],     ap,  bl);
                    mma_bf16(o[jj + 1], ap,  bh + 2);
                    mma_bf16(o[jj + 1], alo, bh + 2);
                    mma_bf16(o[jj + 1], ap,  bl + 2);
                }
            }

            // All warps done reading V -> safe to overwrite with V(kt+1)
            __syncthreads();
            if (kt + 1 < ktiles) { prefetch_v((kt + 1) * 64); CP_COMMIT(); }
        }

        // Epilogue: normalize + store fp32
        float inv0 = __frcp_rn(l0v), inv1 = __frcp_rn(l1v);
        int r0 = q0 + 16 * w + lr;
        #pragma unroll
        for (int jj = 0; jj < 16; jj++) {
            int cc = 8 * jj + lc;
            *(float2*)&out[((size_t)b * Tq + r0) * HSq + cc] =
                make_float2(o[jj][0] * inv0, o[jj][1] * inv0);
            *(float2*)&out[((size_t)b * Tq + r0 + 8) * HSq + cc] =
                make_float2(o[jj][2] * inv1, o[jj][3] * inv1);
        }
    }
}

// ---------------------------------------------------------------------------
extern "C" void kernel_launch(void* const* d_in, const int* in_sizes, int n_in,
                              void* d_out, int out_size)
{
    const float* x  = (const float*)d_in[0];
    const float* Wq = (const float*)d_in[1];
    const float* Wk = (const float*)d_in[2];
    const float* Wv = (const float*)d_in[3];
    float* out = (float*)d_out;

    cudaFuncSetAttribute(proj_mma_kernel, cudaFuncAttributeMaxDynamicSharedMemorySize,
                         PROJ_SMEM);
    cudaFuncSetAttribute(attn_mma_kernel, cudaFuncAttributeMaxDynamicSharedMemorySize,
                         ATTN_SMEM);

    prep_x_kernel<<<BT * Dq / (256 * 8), 256>>>(x);

    dim3 wgrid(Dq / 32, NTOT / 32);
    prep_w_kernel<<<wgrid, dim3(32, 8)>>>(Wq, Wk, Wv);

    dim3 pgrid(BT / 128, 3);
    proj_mma_kernel<<<pgrid, 256, PROJ_SMEM>>>();

    dim3 agrid(16, Bq);
    attn_mma_kernel<<<agrid, 128, ATTN_SMEM>>>(out);
}